// round 1
// baseline (speedup 1.0000x reference)
#include <cuda_runtime.h>
#include <cuda_bf16.h>

#define NB_B    4096
#define NB_OBS  1024
#define NB_HID  1024
#define NB_LAT  512
#define NB_OUT  19
#define NB_E    8
#define NB_NB   3
#define NB_DISP (NB_B*2)   // K=2, every token dispatched exactly twice

#define BM 128
#define BN 128
#define BK 16

// ---------------- scratch (device globals; no cudaMalloc allowed) ----------------
__device__ float g_xa[NB_B*NB_OBS];        // 16 MB
__device__ float g_xb[NB_B*NB_OBS];        // 16 MB
__device__ float g_h [NB_B*NB_HID];        // 16 MB
__device__ float g_lat[NB_B*NB_LAT];       // 8 MB
__device__ float g_xea[NB_DISP*NB_LAT];    // 16 MB
__device__ float g_xeb[NB_DISP*NB_LAT];    // 16 MB
__device__ float g_he [NB_DISP*NB_HID];    // 32 MB
__device__ int   g_tokidx[NB_E*NB_B];
__device__ float g_gatew [NB_E*NB_B];
__device__ int   g_cnt[NB_E];
__device__ int   g_off[NB_E];
__device__ int   g_dtok[NB_DISP];
__device__ float g_dg  [NB_DISP];

// ---------------- SGEMM core: C = epi(A[M,K] @ W[K,N] + bias [, +R]) ----------------
// epi: 0 = bias + relu, 1 = bias + residual R, 2 = bias only
__device__ __forceinline__ void sgemm_core(
    const float* __restrict__ A, const float* __restrict__ W,
    const float* __restrict__ bias, const float* __restrict__ R,
    float* __restrict__ C, int M, int N, int K, int epi)
{
    __shared__ float As[BK][BM];
    __shared__ float Bs[BK][BN];

    const int tid  = threadIdx.x;
    const int row0 = blockIdx.y * BM;
    const int col0 = blockIdx.x * BN;
    const int tx = tid & 15;
    const int ty = tid >> 4;

    const int arow = tid >> 2;          // 0..63 (two passes -> 128 rows)
    const int acol = (tid & 3) * 4;     // 0,4,8,12
    const int brow = tid >> 5;          // 0..7  (two passes -> 16 rows)
    const int bcol = (tid & 31) * 4;    // 0..124

    float acc[8][8];
#pragma unroll
    for (int i = 0; i < 8; i++)
#pragma unroll
        for (int j = 0; j < 8; j++) acc[i][j] = 0.f;

    for (int k0 = 0; k0 < K; k0 += BK) {
#pragma unroll
        for (int s = 0; s < 2; s++) {
            int r  = arow + 64 * s;
            int gr = row0 + r;
            float4 v = make_float4(0.f, 0.f, 0.f, 0.f);
            if (gr < M) v = *(const float4*)(A + (size_t)gr * K + k0 + acol);
            As[acol + 0][r] = v.x;
            As[acol + 1][r] = v.y;
            As[acol + 2][r] = v.z;
            As[acol + 3][r] = v.w;
        }
#pragma unroll
        for (int s = 0; s < 2; s++) {
            int r = brow + 8 * s;
            float4 v = *(const float4*)(W + (size_t)(k0 + r) * N + col0 + bcol);
            *(float4*)&Bs[r][bcol] = v;
        }
        __syncthreads();

#pragma unroll
        for (int kk = 0; kk < BK; kk++) {
            float a[8], b[8];
#pragma unroll
            for (int i = 0; i < 8; i++) a[i] = As[kk][ty * 8 + i];
#pragma unroll
            for (int j = 0; j < 8; j++) b[j] = Bs[kk][tx * 8 + j];
#pragma unroll
            for (int i = 0; i < 8; i++)
#pragma unroll
                for (int j = 0; j < 8; j++)
                    acc[i][j] = fmaf(a[i], b[j], acc[i][j]);
        }
        __syncthreads();
    }

#pragma unroll
    for (int i = 0; i < 8; i++) {
        int gr = row0 + ty * 8 + i;
        if (gr >= M) break;
#pragma unroll
        for (int j = 0; j < 8; j++) {
            int gc = col0 + tx * 8 + j;
            float v = acc[i][j] + bias[gc];
            if (epi == 0)      v = fmaxf(v, 0.f);
            else if (epi == 1) v += R[(size_t)gr * N + gc];
            C[(size_t)gr * N + gc] = v;
        }
    }
}

__global__ void __launch_bounds__(256)
sgemm_kernel(const float* __restrict__ A, const float* __restrict__ W,
             const float* __restrict__ bias, const float* __restrict__ R,
             float* __restrict__ C, int M, int N, int K, int epi)
{
    sgemm_core(A, W, bias, R, C, M, N, K, epi);
}

// Batched-per-expert GEMM over compact dispatched rows. blockIdx.z = expert.
__global__ void __launch_bounds__(256)
esgemm_kernel(const float* __restrict__ Abase, const float* __restrict__ Wbase, long wstride,
              const float* __restrict__ bbase, long bstride,
              const float* __restrict__ Rbase, float* __restrict__ Cbase,
              int N, int K, int epi,
              const int* __restrict__ cnt, const int* __restrict__ off)
{
    int e = blockIdx.z;
    int M = cnt[e];
    if ((int)(blockIdx.y * BM) >= M) return;
    long o = off[e];
    sgemm_core(Abase + o * K,
               Wbase + (long)e * wstride,
               bbase + (long)e * bstride,
               (epi == 1) ? (Rbase + o * N) : nullptr,
               Cbase + o * N, M, N, K, epi);
}

// ---------------- init: zero y columns of output and expert counters ----------------
__global__ void init_kernel(float* __restrict__ out, int* __restrict__ cnt)
{
    int i = blockIdx.x * blockDim.x + threadIdx.x;
    if (i < NB_E) cnt[i] = 0;
    if (i < NB_B * NB_OUT) {
        int b = i / NB_OUT, c = i % NB_OUT;
        out[b * (NB_OUT + 1) + c] = 0.f;
    }
}

// ---------------- gating: logits = lat @ wg, top-2, softmax, append to expert lists ----------------
__global__ void __launch_bounds__(256)
gate_kernel(const float* __restrict__ lat, const float* __restrict__ wg,
            int* __restrict__ tokidx, float* __restrict__ gatew, int* __restrict__ cnt)
{
    __shared__ float swg[NB_LAT * NB_E];
    for (int i = threadIdx.x; i < NB_LAT * NB_E; i += blockDim.x) swg[i] = wg[i];
    __syncthreads();

    int warp = threadIdx.x >> 5, lane = threadIdx.x & 31;
    int b = blockIdx.x * 8 + warp;

    float acc[NB_E];
#pragma unroll
    for (int e = 0; e < NB_E; e++) acc[e] = 0.f;

    for (int k = lane; k < NB_LAT; k += 32) {
        float x = lat[(size_t)b * NB_LAT + k];
#pragma unroll
        for (int e = 0; e < NB_E; e++) acc[e] = fmaf(x, swg[k * NB_E + e], acc[e]);
    }
#pragma unroll
    for (int e = 0; e < NB_E; e++)
#pragma unroll
        for (int o = 16; o; o >>= 1) acc[e] += __shfl_xor_sync(0xFFFFFFFFu, acc[e], o);

    if (lane == 0) {
        int e0 = 0; float v0 = acc[0];
        for (int e = 1; e < NB_E; e++) if (acc[e] > v0) { v0 = acc[e]; e0 = e; }
        int e1 = -1; float v1 = -3.4e38f;
        for (int e = 0; e < NB_E; e++) if (e != e0 && acc[e] > v1) { v1 = acc[e]; e1 = e; }
        float w1 = expf(v1 - v0);          // softmax over the 2 selected logits
        float s  = 1.f + w1;
        float w0 = 1.f / s;  w1 = w1 / s;
        int p0 = atomicAdd(&cnt[e0], 1); tokidx[e0 * NB_B + p0] = b; gatew[e0 * NB_B + p0] = w0;
        int p1 = atomicAdd(&cnt[e1], 1); tokidx[e1 * NB_B + p1] = b; gatew[e1 * NB_B + p1] = w1;
    }
}

__global__ void scan_kernel(const int* __restrict__ cnt, int* __restrict__ off)
{
    if (threadIdx.x == 0) {
        int s = 0;
        for (int e = 0; e < NB_E; e++) { off[e] = s; s += cnt[e]; }
    }
}

// ---------------- gather dispatched latent rows into compact per-expert segments ----------------
__global__ void __launch_bounds__(256)
gather_kernel(const float* __restrict__ lat,
              const int* __restrict__ tokidx, const float* __restrict__ gatew,
              const int* __restrict__ cnt, const int* __restrict__ off,
              float* __restrict__ xe, int* __restrict__ dtok, float* __restrict__ dg)
{
    int e = blockIdx.x;
    int r = blockIdx.y * 8 + (threadIdx.x >> 5);
    int lane = threadIdx.x & 31;
    if (r >= cnt[e]) return;
    int tok = tokidx[e * NB_B + r];
    int dst = off[e] + r;
    const float4* src = (const float4*)(lat + (size_t)tok * NB_LAT);
    float4*       d   = (float4*)(xe + (size_t)dst * NB_LAT);
#pragma unroll
    for (int i = 0; i < 4; i++) d[lane + 32 * i] = src[lane + 32 * i];
    if (lane == 0) { dtok[dst] = tok; dg[dst] = gatew[e * NB_B + r]; }
}

// ---------------- expert head: y[tok] += g * (xe @ Wf[e] + bf[e])  (scatter-add) ----------------
__global__ void __launch_bounds__(256)
expert_final_kernel(const float* __restrict__ xe, const float* __restrict__ Wf,
                    const float* __restrict__ bf,
                    const int* __restrict__ cnt, const int* __restrict__ off,
                    const int* __restrict__ dtok, const float* __restrict__ dg,
                    float* __restrict__ out)
{
    int e = blockIdx.x;
    __shared__ float sW[NB_LAT * NB_OUT];
    for (int i = threadIdx.x; i < NB_LAT * NB_OUT; i += blockDim.x)
        sW[i] = Wf[(size_t)e * NB_LAT * NB_OUT + i];
    __syncthreads();

    int r = blockIdx.y * 8 + (threadIdx.x >> 5);
    int lane = threadIdx.x & 31;
    if (r >= cnt[e]) return;
    int dst = off[e] + r;

    float acc[NB_OUT];
#pragma unroll
    for (int c = 0; c < NB_OUT; c++) acc[c] = 0.f;

    const float* x = xe + (size_t)dst * NB_LAT;
#pragma unroll
    for (int i = 0; i < NB_LAT / 32; i++) {
        int k = lane + 32 * i;
        float xv = x[k];
#pragma unroll
        for (int c = 0; c < NB_OUT; c++) acc[c] = fmaf(xv, sW[k * NB_OUT + c], acc[c]);
    }
#pragma unroll
    for (int c = 0; c < NB_OUT; c++)
#pragma unroll
        for (int o = 16; o; o >>= 1) acc[c] += __shfl_xor_sync(0xFFFFFFFFu, acc[c], o);

    if (lane == 0) {
        int tok = dtok[dst];
        float g = dg[dst];
#pragma unroll
        for (int c = 0; c < NB_OUT; c++)
            atomicAdd(&out[tok * (NB_OUT + 1) + c], g * (acc[c] + bf[e * NB_OUT + c]));
    }
}

// ---------------- value head: out[:,19] = xv @ Wf + bf ----------------
__global__ void __launch_bounds__(256)
value_final_kernel(const float* __restrict__ xv, const float* __restrict__ Wf,
                   const float* __restrict__ bf, float* __restrict__ out)
{
    int b = blockIdx.x * 8 + (threadIdx.x >> 5);
    int lane = threadIdx.x & 31;
    float acc = 0.f;
    const float* x = xv + (size_t)b * NB_OBS;
#pragma unroll
    for (int i = 0; i < NB_OBS / 32; i++) acc = fmaf(x[lane + 32 * i], Wf[lane + 32 * i], acc);
#pragma unroll
    for (int o = 16; o; o >>= 1) acc += __shfl_xor_sync(0xFFFFFFFFu, acc, o);
    if (lane == 0) out[b * (NB_OUT + 1) + NB_OUT] = acc + bf[0];
}

// ---------------- SparseDispatcher.combine quirk: y==0 -> EPS ----------------
__global__ void eps_kernel(float* __restrict__ out)
{
    int i = blockIdx.x * blockDim.x + threadIdx.x;
    if (i < NB_B * NB_OUT) {
        int b = i / NB_OUT, c = i % NB_OUT;
        float* p = &out[b * (NB_OUT + 1) + c];
        if (*p == 0.f) *p = 2.2204460492503131e-16f;
    }
}

// =====================================================================================
extern "C" void kernel_launch(void* const* d_in, const int* in_sizes, int n_in,
                              void* d_out, int out_size)
{
    const float* obs    = (const float*)d_in[0];
    const float* encW1  = (const float*)d_in[1];
    const float* encb1  = (const float*)d_in[2];
    const float* encW2  = (const float*)d_in[3];
    const float* encb2  = (const float*)d_in[4];
    const float* encWf  = (const float*)d_in[5];
    const float* encbf  = (const float*)d_in[6];
    const float* expW1  = (const float*)d_in[7];
    const float* expb1  = (const float*)d_in[8];
    const float* expW2  = (const float*)d_in[9];
    const float* expb2  = (const float*)d_in[10];
    const float* expWf  = (const float*)d_in[11];
    const float* expbf  = (const float*)d_in[12];
    const float* valW1  = (const float*)d_in[13];
    const float* valb1  = (const float*)d_in[14];
    const float* valW2  = (const float*)d_in[15];
    const float* valb2  = (const float*)d_in[16];
    const float* valWf  = (const float*)d_in[17];
    const float* valbf  = (const float*)d_in[18];
    const float* wgate  = (const float*)d_in[19];
    float* out = (float*)d_out;

    float *xa, *xb, *h, *lat, *xea, *xeb, *he, *gatew, *dg;
    int *tokidx, *cnt, *off, *dtok;
    cudaGetSymbolAddress((void**)&xa,     g_xa);
    cudaGetSymbolAddress((void**)&xb,     g_xb);
    cudaGetSymbolAddress((void**)&h,      g_h);
    cudaGetSymbolAddress((void**)&lat,    g_lat);
    cudaGetSymbolAddress((void**)&xea,    g_xea);
    cudaGetSymbolAddress((void**)&xeb,    g_xeb);
    cudaGetSymbolAddress((void**)&he,     g_he);
    cudaGetSymbolAddress((void**)&tokidx, g_tokidx);
    cudaGetSymbolAddress((void**)&gatew,  g_gatew);
    cudaGetSymbolAddress((void**)&cnt,    g_cnt);
    cudaGetSymbolAddress((void**)&off,    g_off);
    cudaGetSymbolAddress((void**)&dtok,   g_dtok);
    cudaGetSymbolAddress((void**)&dg,     g_dg);

    init_kernel<<<(NB_B * NB_OUT + 255) / 256, 256>>>(out, cnt);

    // -------- encoder ResNet: obs -> latent --------
    dim3 gh(NB_HID / BN, NB_B / BM);   // N=1024
    dim3 go(NB_OBS / BN, NB_B / BM);   // N=1024
    dim3 gl(NB_LAT / BN, NB_B / BM);   // N=512

    sgemm_kernel<<<gh, 256>>>(obs, encW1,                     encb1,          nullptr, h,  NB_B, NB_HID, NB_OBS, 0);
    sgemm_kernel<<<go, 256>>>(h,   encW2,                     encb2,          obs,     xa, NB_B, NB_OBS, NB_HID, 1);
    sgemm_kernel<<<gh, 256>>>(xa,  encW1 + 1 * NB_OBS * NB_HID, encb1 + NB_HID,     nullptr, h,  NB_B, NB_HID, NB_OBS, 0);
    sgemm_kernel<<<go, 256>>>(h,   encW2 + 1 * NB_HID * NB_OBS, encb2 + NB_OBS,     xa,      xb, NB_B, NB_OBS, NB_HID, 1);
    sgemm_kernel<<<gh, 256>>>(xb,  encW1 + 2 * NB_OBS * NB_HID, encb1 + 2 * NB_HID, nullptr, h,  NB_B, NB_HID, NB_OBS, 0);
    sgemm_kernel<<<go, 256>>>(h,   encW2 + 2 * NB_HID * NB_OBS, encb2 + 2 * NB_OBS, xb,      xa, NB_B, NB_OBS, NB_HID, 1);
    sgemm_kernel<<<gl, 256>>>(xa,  encWf, encbf, nullptr, lat, NB_B, NB_LAT, NB_OBS, 2);

    // -------- gating + dispatch --------
    gate_kernel<<<NB_B / 8, 256>>>(lat, wgate, tokidx, gatew, cnt);
    scan_kernel<<<1, 32>>>(cnt, off);
    gather_kernel<<<dim3(NB_E, NB_B / 8), 256>>>(lat, tokidx, gatew, cnt, off, xea, dtok, dg);

    // -------- expert ResNets on dispatched tokens --------
    const long w1s = (long)NB_NB * NB_LAT * NB_HID, b1s = (long)NB_NB * NB_HID;
    const long w2s = (long)NB_NB * NB_HID * NB_LAT, b2s = (long)NB_NB * NB_LAT;
    dim3 eg1(NB_HID / BN, NB_B / BM, NB_E);
    dim3 eg2(NB_LAT / BN, NB_B / BM, NB_E);

    float* ex_cur = xea;
    float* ex_nxt = xeb;
    for (int blk = 0; blk < NB_NB; blk++) {
        esgemm_kernel<<<eg1, 256>>>(ex_cur, expW1 + (long)blk * NB_LAT * NB_HID, w1s,
                                    expb1 + blk * NB_HID, b1s,
                                    nullptr, he, NB_HID, NB_LAT, 0, cnt, off);
        esgemm_kernel<<<eg2, 256>>>(he, expW2 + (long)blk * NB_HID * NB_LAT, w2s,
                                    expb2 + blk * NB_LAT, b2s,
                                    ex_cur, ex_nxt, NB_LAT, NB_HID, 1, cnt, off);
        float* t = ex_cur; ex_cur = ex_nxt; ex_nxt = t;
    }
    expert_final_kernel<<<dim3(NB_E, NB_B / 8), 256>>>(ex_cur, expWf, expbf, cnt, off, dtok, dg, out);

    // -------- value ResNet: obs -> scalar --------
    sgemm_kernel<<<gh, 256>>>(obs, valW1,                     valb1,          nullptr, h,  NB_B, NB_HID, NB_OBS, 0);
    sgemm_kernel<<<go, 256>>>(h,   valW2,                     valb2,          obs,     xa, NB_B, NB_OBS, NB_HID, 1);
    sgemm_kernel<<<gh, 256>>>(xa,  valW1 + 1 * NB_OBS * NB_HID, valb1 + NB_HID,     nullptr, h,  NB_B, NB_HID, NB_OBS, 0);
    sgemm_kernel<<<go, 256>>>(h,   valW2 + 1 * NB_HID * NB_OBS, valb2 + NB_OBS,     xa,      xb, NB_B, NB_OBS, NB_HID, 1);
    sgemm_kernel<<<gh, 256>>>(xb,  valW1 + 2 * NB_OBS * NB_HID, valb1 + 2 * NB_HID, nullptr, h,  NB_B, NB_HID, NB_OBS, 0);
    sgemm_kernel<<<go, 256>>>(h,   valW2 + 2 * NB_HID * NB_OBS, valb2 + 2 * NB_OBS, xb,      xa, NB_B, NB_OBS, NB_HID, 1);
    value_final_kernel<<<NB_B / 8, 256>>>(xa, valWf, valbf, out);

    // -------- combine quirk --------
    eps_kernel<<<(NB_B * NB_OUT + 255) / 256, 256>>>(out);
}